// round 3
// baseline (speedup 1.0000x reference)
#include <cuda_runtime.h>
#include <cuda_bf16.h>

// ResidualGridVolume: out[n,c] = trilinear((base+detail)[c], xyz[n]/1.5), C=28, R=128.
//
// Strategy:
//   Kernel 1 (fuse): transpose channel-major (C, D, H, W) x 2 volumes into a
//     single voxel-major volume g_vol[z][y][x][c] with channel stride padded to
//     32 floats -> each voxel = exactly one 128B cache line, 128B-aligned.
//     Reads fully coalesced (consecutive voxels are consecutive within each
//     channel plane), writes vectorized float4 including zero padding.
//   Kernel 2 (sample): one thread per point; 8 corner lines x 7 float4 loads,
//     corner-major order so the 7 loads of a line hit L1 back-to-back;
//     7 float4 accumulators; 7 float4 stores to the (N,28) output (row = 112B,
//     divisible by 16 -> float4 stores are aligned for every n).
//
// Input range: |xyz| <= 1.5*0.99 -> pix in [0.635, 126.365] -> all 8 corners
// in-bounds; clamps below are safety only (zeros-padding never triggers).

static constexpr int R      = 128;
static constexpr int R3     = R * R * R;      // 2,097,152 voxels
static constexpr int CH     = 28;             // 1 density + 27 SH
static constexpr int CS     = 32;             // padded channel stride (floats)

// 256 MB scratch: __device__ global (no runtime allocation).
__device__ __align__(256) float g_vol[(size_t)R3 * CS];

// ---------------------------------------------------------------------------
// Kernel 1: fuse base+detail and transpose to voxel-major, channel-padded.
// ---------------------------------------------------------------------------
__global__ void fuse_transpose_kernel(const float* __restrict__ base_density,
                                      const float* __restrict__ base_sh,
                                      const float* __restrict__ detail_density,
                                      const float* __restrict__ detail_sh) {
    int v = blockIdx.x * blockDim.x + threadIdx.x;
    if (v >= R3) return;

    float vals[CS];
    vals[0] = base_density[v] + detail_density[v];
#pragma unroll
    for (int c = 0; c < 27; c++) {
        size_t off = (size_t)c * R3 + (size_t)v;
        vals[c + 1] = base_sh[off] + detail_sh[off];
    }
#pragma unroll
    for (int c = CH; c < CS; c++) vals[c] = 0.0f;

    float4* dst = reinterpret_cast<float4*>(g_vol + (size_t)v * CS);
#pragma unroll
    for (int i = 0; i < CS / 4; i++)
        dst[i] = reinterpret_cast<const float4*>(vals)[i];
}

// ---------------------------------------------------------------------------
// Kernel 2: trilinear gather, one thread per point.
// ---------------------------------------------------------------------------
__global__ void __launch_bounds__(256)
sample_kernel(const float* __restrict__ xyz, float* __restrict__ out, int N) {
    int n = blockIdx.x * blockDim.x + threadIdx.x;
    if (n >= N) return;

    const float inv_bound = 1.0f / 1.5f;
    float gx = xyz[3 * n + 0] * inv_bound;
    float gy = xyz[3 * n + 1] * inv_bound;
    float gz = xyz[3 * n + 2] * inv_bound;

    // align_corners=True: pix = (g + 1) * 0.5 * (size - 1)
    float px = (gx + 1.0f) * 0.5f * 127.0f;
    float py = (gy + 1.0f) * 0.5f * 127.0f;
    float pz = (gz + 1.0f) * 0.5f * 127.0f;

    float fx0 = floorf(px), fy0 = floorf(py), fz0 = floorf(pz);
    float fx = px - fx0, fy = py - fy0, fz = pz - fz0;

    int x0 = min(max((int)fx0, 0), R - 2);
    int y0 = min(max((int)fy0, 0), R - 2);
    int z0 = min(max((int)fz0, 0), R - 2);

    float wx1 = fx, wx0 = 1.0f - fx;
    float wy1 = fy, wy0 = 1.0f - fy;
    float wz1 = fz, wz0 = 1.0f - fz;

    float w[8];
    w[0] = wz0 * wy0 * wx0;
    w[1] = wz0 * wy0 * wx1;
    w[2] = wz0 * wy1 * wx0;
    w[3] = wz0 * wy1 * wx1;
    w[4] = wz1 * wy0 * wx0;
    w[5] = wz1 * wy0 * wx1;
    w[6] = wz1 * wy1 * wx0;
    w[7] = wz1 * wy1 * wx1;

    const size_t OX = CS;                 // +1 in x
    const size_t OY = (size_t)R * CS;     // +1 in y
    const size_t OZ = (size_t)R * R * CS; // +1 in z
    size_t base = (((size_t)z0 * R + (size_t)y0) * R + (size_t)x0) * CS;

    size_t addr[8];
    addr[0] = base;
    addr[1] = base + OX;
    addr[2] = base + OY;
    addr[3] = base + OY + OX;
    addr[4] = base + OZ;
    addr[5] = base + OZ + OX;
    addr[6] = base + OZ + OY;
    addr[7] = base + OZ + OY + OX;

    float4 acc[7];
#pragma unroll
    for (int i = 0; i < 7; i++) acc[i] = make_float4(0.f, 0.f, 0.f, 0.f);

#pragma unroll
    for (int k = 0; k < 8; k++) {
        const float4* src = reinterpret_cast<const float4*>(g_vol + addr[k]);
        float wk = w[k];
#pragma unroll
        for (int i = 0; i < 7; i++) {
            float4 f = __ldg(src + i);
            acc[i].x = fmaf(wk, f.x, acc[i].x);
            acc[i].y = fmaf(wk, f.y, acc[i].y);
            acc[i].z = fmaf(wk, f.z, acc[i].z);
            acc[i].w = fmaf(wk, f.w, acc[i].w);
        }
    }

    // (N, 28) row-major output; 28 floats = 112 B, 16B-aligned for every n.
    float4* o = reinterpret_cast<float4*>(out + (size_t)n * CH);
#pragma unroll
    for (int i = 0; i < 7; i++) o[i] = acc[i];
}

// ---------------------------------------------------------------------------
// Launch: inputs per metadata order:
//   [0] xyz (N*3), [1] base_density (128^3), [2] base_sh (27*128^3),
//   [3] detail_density, [4] detail_sh. Output: float32, N*28.
// ---------------------------------------------------------------------------
extern "C" void kernel_launch(void* const* d_in, const int* in_sizes, int n_in,
                              void* d_out, int out_size) {
    const float* xyz            = (const float*)d_in[0];
    const float* base_density   = (const float*)d_in[1];
    const float* base_sh        = (const float*)d_in[2];
    const float* detail_density = (const float*)d_in[3];
    const float* detail_sh      = (const float*)d_in[4];
    float* out = (float*)d_out;

    int N = in_sizes[0] / 3;

    {
        int threads = 256;
        int blocks = (R3 + threads - 1) / threads;
        fuse_transpose_kernel<<<blocks, threads>>>(base_density, base_sh,
                                                   detail_density, detail_sh);
    }
    {
        int threads = 256;
        int blocks = (N + threads - 1) / threads;
        sample_kernel<<<blocks, threads>>>(xyz, out, N);
    }
}

// round 4
// speedup vs baseline: 3.0900x; 3.0900x over previous
#include <cuda_runtime.h>
#include <cuda_fp16.h>
#include <cuda_bf16.h>

// ResidualGridVolume: out[n,c] = trilinear((base+detail)[c], xyz[n]/1.5), C=28, R=128.
//
// R3 learning: fp32 voxel-major volume (256 MB) has ZERO L2 reuse under random
// point order -> every corner fetch is a random 128B DRAM access -> 1585 us,
// DRAM 82% busy. Fix: fp16 volume, 28 ch unpadded = 56 B/voxel = 112 MB total,
// which FITS IN L2 (126 MB). The fuse kernel's stores populate L2; the sample
// kernel then reads corners from L2 at LTS bandwidth. Streaming traffic
// (fuse inputs, xyz, output) uses .cs hints so it does not evict the volume.

static constexpr int R   = 128;
static constexpr int R3  = R * R * R;     // 2,097,152 voxels
static constexpr int CH  = 28;            // 1 density + 27 SH

// 112 MB scratch: __device__ global (no runtime allocation). 56 B per voxel.
__device__ __align__(256) __half g_volh[(size_t)R3 * CH];

// ---------------------------------------------------------------------------
// Kernel 1: fuse base+detail, convert to fp16, write voxel-major.
// Reads are coalesced per channel plane; writes are 7x uint2 per voxel
// (56 B, 8B-aligned). Input reads use __ldcs (streaming) to avoid polluting
// L2; writes are normal so the volume lands resident in L2.
// ---------------------------------------------------------------------------
__global__ void fuse_transpose_kernel(const float* __restrict__ base_density,
                                      const float* __restrict__ base_sh,
                                      const float* __restrict__ detail_density,
                                      const float* __restrict__ detail_sh) {
    int v = blockIdx.x * blockDim.x + threadIdx.x;
    if (v >= R3) return;

    __half h[CH];
    h[0] = __float2half_rn(__ldcs(base_density + v) + __ldcs(detail_density + v));
#pragma unroll
    for (int c = 0; c < 27; c++) {
        size_t off = (size_t)c * R3 + (size_t)v;
        h[c + 1] = __float2half_rn(__ldcs(base_sh + off) + __ldcs(detail_sh + off));
    }

    // Pack 28 halves into 7 uint2 (56 B), 8B-aligned store.
    unsigned words[14];
#pragma unroll
    for (int i = 0; i < 14; i++) {
        __half2 p = __halves2half2(h[2 * i], h[2 * i + 1]);
        words[i] = *reinterpret_cast<unsigned*>(&p);
    }
    uint2* dst = reinterpret_cast<uint2*>(g_volh + (size_t)v * CH);
#pragma unroll
    for (int i = 0; i < 7; i++)
        dst[i] = make_uint2(words[2 * i], words[2 * i + 1]);
}

// ---------------------------------------------------------------------------
// Kernel 2: trilinear gather, one thread per point. Corner-major loop,
// x-pair corners consecutive (their 56B spans overlap sectors -> L1 dedups).
// fp32 accumulation; streaming stores for the (N,28) output.
// ---------------------------------------------------------------------------
__global__ void __launch_bounds__(256)
sample_kernel(const float* __restrict__ xyz, float* __restrict__ out, int N) {
    int n = blockIdx.x * blockDim.x + threadIdx.x;
    if (n >= N) return;

    const float inv_bound = 1.0f / 1.5f;
    float gx = __ldcs(xyz + 3 * n + 0) * inv_bound;
    float gy = __ldcs(xyz + 3 * n + 1) * inv_bound;
    float gz = __ldcs(xyz + 3 * n + 2) * inv_bound;

    // align_corners=True: pix = (g + 1) * 0.5 * (size - 1)
    float px = (gx + 1.0f) * 0.5f * 127.0f;
    float py = (gy + 1.0f) * 0.5f * 127.0f;
    float pz = (gz + 1.0f) * 0.5f * 127.0f;

    float fx0 = floorf(px), fy0 = floorf(py), fz0 = floorf(pz);
    float fx = px - fx0, fy = py - fy0, fz = pz - fz0;

    // Inputs are interior (|g| <= 0.99) -> clamps are safety only.
    int x0 = min(max((int)fx0, 0), R - 2);
    int y0 = min(max((int)fy0, 0), R - 2);
    int z0 = min(max((int)fz0, 0), R - 2);

    float wx1 = fx, wx0 = 1.0f - fx;
    float wy1 = fy, wy0 = 1.0f - fy;
    float wz1 = fz, wz0 = 1.0f - fz;

    float w[8];
    w[0] = wz0 * wy0 * wx0;   // (z0, y0, x0)
    w[1] = wz0 * wy0 * wx1;   // (z0, y0, x1)
    w[2] = wz0 * wy1 * wx0;
    w[3] = wz0 * wy1 * wx1;
    w[4] = wz1 * wy0 * wx0;
    w[5] = wz1 * wy0 * wx1;
    w[6] = wz1 * wy1 * wx0;
    w[7] = wz1 * wy1 * wx1;

    const size_t OX = CH;                 // +1 in x (56 B)
    const size_t OY = (size_t)R * CH;     // +1 in y
    const size_t OZ = (size_t)R * R * CH; // +1 in z
    size_t base = (((size_t)z0 * R + (size_t)y0) * R + (size_t)x0) * CH;

    size_t addr[8];
    addr[0] = base;
    addr[1] = base + OX;
    addr[2] = base + OY;
    addr[3] = base + OY + OX;
    addr[4] = base + OZ;
    addr[5] = base + OZ + OX;
    addr[6] = base + OZ + OY;
    addr[7] = base + OZ + OY + OX;

    float acc[CH];
#pragma unroll
    for (int i = 0; i < CH; i++) acc[i] = 0.0f;

#pragma unroll
    for (int k = 0; k < 8; k++) {
        const uint2* src = reinterpret_cast<const uint2*>(g_volh + addr[k]);
        float wk = w[k];
#pragma unroll
        for (int i = 0; i < 7; i++) {
            uint2 q = __ldg(src + i);
            __half2 h0 = *reinterpret_cast<__half2*>(&q.x);
            __half2 h1 = *reinterpret_cast<__half2*>(&q.y);
            float2 f0 = __half22float2(h0);
            float2 f1 = __half22float2(h1);
            acc[4 * i + 0] = fmaf(wk, f0.x, acc[4 * i + 0]);
            acc[4 * i + 1] = fmaf(wk, f0.y, acc[4 * i + 1]);
            acc[4 * i + 2] = fmaf(wk, f1.x, acc[4 * i + 2]);
            acc[4 * i + 3] = fmaf(wk, f1.y, acc[4 * i + 3]);
        }
    }

    // (N, 28) row-major output; 112 B rows -> float4 stores aligned for all n.
    // Streaming stores: do not evict the L2-resident volume.
    float4* o = reinterpret_cast<float4*>(out + (size_t)n * CH);
#pragma unroll
    for (int i = 0; i < 7; i++) {
        float4 v4 = make_float4(acc[4 * i + 0], acc[4 * i + 1],
                                acc[4 * i + 2], acc[4 * i + 3]);
        __stcs(o + i, v4);
    }
}

// ---------------------------------------------------------------------------
// Launch. Inputs in metadata order:
//   [0] xyz (N*3), [1] base_density (128^3), [2] base_sh (27*128^3),
//   [3] detail_density, [4] detail_sh. Output: float32, N*28.
// ---------------------------------------------------------------------------
extern "C" void kernel_launch(void* const* d_in, const int* in_sizes, int n_in,
                              void* d_out, int out_size) {
    const float* xyz            = (const float*)d_in[0];
    const float* base_density   = (const float*)d_in[1];
    const float* base_sh        = (const float*)d_in[2];
    const float* detail_density = (const float*)d_in[3];
    const float* detail_sh      = (const float*)d_in[4];
    float* out = (float*)d_out;

    int N = in_sizes[0] / 3;

    {
        int threads = 256;
        int blocks = (R3 + threads - 1) / threads;
        fuse_transpose_kernel<<<blocks, threads>>>(base_density, base_sh,
                                                   detail_density, detail_sh);
    }
    {
        int threads = 256;
        int blocks = (N + threads - 1) / threads;
        sample_kernel<<<blocks, threads>>>(xyz, out, N);
    }
}

// round 5
// speedup vs baseline: 6.2823x; 2.0331x over previous
#include <cuda_runtime.h>
#include <cuda_fp16.h>
#include <cuda_bf16.h>

// ResidualGridVolume: out[n,c] = trilinear((base+detail)[c], xyz[n]/1.5), C=28, R=128.
//
// R4 learning: sample kernel was L1tex-wavefront bound (L1=91.9%): 56 divergent
// loads/point -> 56 wf/point -> 410 us (model-exact). Fix: quad-cooperative
// gather. Voxel padded to 64 B (32 fp16 ch, 134 MB). 4 threads per point;
// thread j loads 16B chunk j of each corner voxel -> one warp load instruction
// covers 8 points x one 64B corner = ~8 lines -> ~8 wf/point (7x fewer).
// Thread j owns channels 8j..8j+7 for ALL corners -> no cross-thread
// reduction, no shuffles. Output rows of a warp are 8 consecutive 112B rows.

static constexpr int R   = 128;
static constexpr int R3  = R * R * R;     // 2,097,152 voxels
static constexpr int CH  = 28;            // 1 density + 27 SH
static constexpr int CSB = 32;            // padded channel stride (halves) = 64 B

// 134 MB scratch: __device__ global (no runtime allocation).
__device__ __align__(256) __half g_volh[(size_t)R3 * CSB];

// ---------------------------------------------------------------------------
// Kernel 1: fuse base+detail -> fp16, voxel-major, 64B-padded voxels.
// Streaming reads (__ldcs) so inputs don't evict the volume from L2;
// normal stores so the volume lands L2-resident.
// ---------------------------------------------------------------------------
__global__ void fuse_transpose_kernel(const float* __restrict__ base_density,
                                      const float* __restrict__ base_sh,
                                      const float* __restrict__ detail_density,
                                      const float* __restrict__ detail_sh) {
    int v = blockIdx.x * blockDim.x + threadIdx.x;
    if (v >= R3) return;

    __half h[CSB];
    h[0] = __float2half_rn(__ldcs(base_density + v) + __ldcs(detail_density + v));
#pragma unroll
    for (int c = 0; c < 27; c++) {
        size_t off = (size_t)c * R3 + (size_t)v;
        h[c + 1] = __float2half_rn(__ldcs(base_sh + off) + __ldcs(detail_sh + off));
    }
#pragma unroll
    for (int c = CH; c < CSB; c++) h[c] = __float2half_rn(0.0f);

    // 64 B per voxel -> 4 aligned uint4 stores.
    uint4* dst = reinterpret_cast<uint4*>(g_volh + (size_t)v * CSB);
#pragma unroll
    for (int i = 0; i < 4; i++)
        dst[i] = reinterpret_cast<const uint4*>(h)[i];
}

// ---------------------------------------------------------------------------
// Kernel 2: quad-cooperative trilinear gather. 4 threads per point; thread
// j = tid&3 owns 16B chunk j (channels 8j..8j+7). Weight math is redundant
// within a quad (costs no extra warp instructions).
// ---------------------------------------------------------------------------
__global__ void __launch_bounds__(256)
sample_kernel(const float* __restrict__ xyz, float* __restrict__ out, int N) {
    int t = blockIdx.x * blockDim.x + threadIdx.x;
    int p = t >> 2;          // point index
    int j = t & 3;           // chunk index (channels 8j..8j+7)
    if (p >= N) return;

    // Quad-broadcast reads of this point's coords.
    const float inv_bound = 1.0f / 1.5f;
    float gx = __ldg(xyz + 3 * p + 0) * inv_bound;
    float gy = __ldg(xyz + 3 * p + 1) * inv_bound;
    float gz = __ldg(xyz + 3 * p + 2) * inv_bound;

    // align_corners=True: pix = (g + 1) * 0.5 * (size - 1)
    float px = (gx + 1.0f) * 0.5f * 127.0f;
    float py = (gy + 1.0f) * 0.5f * 127.0f;
    float pz = (gz + 1.0f) * 0.5f * 127.0f;

    float fx0 = floorf(px), fy0 = floorf(py), fz0 = floorf(pz);
    float fx = px - fx0, fy = py - fy0, fz = pz - fz0;

    // Inputs are interior (|g| <= 0.99); clamps are safety only.
    int x0 = min(max((int)fx0, 0), R - 2);
    int y0 = min(max((int)fy0, 0), R - 2);
    int z0 = min(max((int)fz0, 0), R - 2);

    float wx1 = fx, wx0 = 1.0f - fx;
    float wy1 = fy, wy0 = 1.0f - fy;
    float wz1 = fz, wz0 = 1.0f - fz;

    float w[8];
    w[0] = wz0 * wy0 * wx0;
    w[1] = wz0 * wy0 * wx1;
    w[2] = wz0 * wy1 * wx0;
    w[3] = wz0 * wy1 * wx1;
    w[4] = wz1 * wy0 * wx0;
    w[5] = wz1 * wy0 * wx1;
    w[6] = wz1 * wy1 * wx0;
    w[7] = wz1 * wy1 * wx1;

    const unsigned OX = CSB;               // +1 in x (in halves)
    const unsigned OY = R * CSB;           // +1 in y
    const unsigned OZ = R * R * CSB;       // +1 in z
    unsigned base = (((unsigned)z0 * R + (unsigned)y0) * R + (unsigned)x0) * CSB;

    unsigned offs[8];
    offs[0] = base;
    offs[1] = base + OX;
    offs[2] = base + OY;
    offs[3] = base + OY + OX;
    offs[4] = base + OZ;
    offs[5] = base + OZ + OX;
    offs[6] = base + OZ + OY;
    offs[7] = base + OZ + OY + OX;

    // Issue all 8 corner loads first (MLP = 8), then accumulate.
    uint4 q[8];
#pragma unroll
    for (int k = 0; k < 8; k++)
        q[k] = __ldg(reinterpret_cast<const uint4*>(g_volh + (size_t)offs[k]) + j);

    float acc[8];
#pragma unroll
    for (int i = 0; i < 8; i++) acc[i] = 0.0f;

#pragma unroll
    for (int k = 0; k < 8; k++) {
        float wk = w[k];
        const __half2* h2 = reinterpret_cast<const __half2*>(&q[k]);
#pragma unroll
        for (int i = 0; i < 4; i++) {
            float2 f = __half22float2(h2[i]);
            acc[2 * i + 0] = fmaf(wk, f.x, acc[2 * i + 0]);
            acc[2 * i + 1] = fmaf(wk, f.y, acc[2 * i + 1]);
        }
    }

    // Output row = 112 B; chunk j writes bytes [32j, 32j+32) (j<3) or
    // [96, 112) (j==3, channels 24-27). All stores 16B-aligned.
    float* orow = out + (size_t)p * CH + 8 * j;
    __stcs(reinterpret_cast<float4*>(orow),
           make_float4(acc[0], acc[1], acc[2], acc[3]));
    if (j < 3) {
        __stcs(reinterpret_cast<float4*>(orow + 4),
               make_float4(acc[4], acc[5], acc[6], acc[7]));
    }
}

// ---------------------------------------------------------------------------
// Launch. Inputs in metadata order:
//   [0] xyz (N*3), [1] base_density (128^3), [2] base_sh (27*128^3),
//   [3] detail_density, [4] detail_sh. Output: float32, N*28.
// ---------------------------------------------------------------------------
extern "C" void kernel_launch(void* const* d_in, const int* in_sizes, int n_in,
                              void* d_out, int out_size) {
    const float* xyz            = (const float*)d_in[0];
    const float* base_density   = (const float*)d_in[1];
    const float* base_sh        = (const float*)d_in[2];
    const float* detail_density = (const float*)d_in[3];
    const float* detail_sh      = (const float*)d_in[4];
    float* out = (float*)d_out;

    int N = in_sizes[0] / 3;

    {
        int threads = 256;
        int blocks = (R3 + threads - 1) / threads;
        fuse_transpose_kernel<<<blocks, threads>>>(base_density, base_sh,
                                                   detail_density, detail_sh);
    }
    {
        long long total = 4LL * N;   // 4 threads per point
        int threads = 256;
        int blocks = (int)((total + threads - 1) / threads);
        sample_kernel<<<blocks, threads>>>(xyz, out, N);
    }
}